// round 10
// baseline (speedup 1.0000x reference)
#include <cuda_runtime.h>
#include <cuda_bf16.h>
#include <cstdint>

// Problem constants
#define BB 64
#define SS 4096
#define HH 256
#define AA 128
#define NTOK (BB * SS)          // 262144 tokens

#define PADK 72                 // bf16 elems per smem row (144B, conflict-free)
#define NPART 8                 // context partial slices per batch

// ---------------- scratch (device globals; no allocation allowed) ----------
__device__ float g_scores[NTOK];                    // [B,S] pre-entmax scores
__device__ float g_partial[BB * NPART * HH];        // context partials
__device__ int   g_nzidx[NTOK];                     // compacted support idx
__device__ float g_nzw[NTOK];                       // compacted support w
__device__ int   g_nzcnt[BB];                       // support count per batch
__device__ int   g_ctr[BB];                         // ctx slice arrival counter
__device__ int   g_scnt[BB];                        // scores CTA arrival counter
// W1 pre-converted to bf16 hi/lo, padded chunk layout: [4 chunks][128 n][72]
__device__ __nv_bfloat16 g_Bhi[4 * 128 * PADK];
__device__ __nv_bfloat16 g_Blo[4 * 128 * PADK];

// ---------------- PTX helpers ----------------------------------------------
__device__ __forceinline__ uint32_t s2u(const void* p) {
    uint32_t a;
    asm("{ .reg .u64 t; cvta.to.shared.u64 t, %1; cvt.u32.u64 %0, t; }"
        : "=r"(a) : "l"(p));
    return a;
}

#define LDSM_X4(r0, r1, r2, r3, addr)                                        \
    asm volatile("ldmatrix.sync.aligned.m8n8.x4.shared.b16 {%0,%1,%2,%3}, [%4];" \
                 : "=r"(r0), "=r"(r1), "=r"(r2), "=r"(r3) : "r"(addr))

#define MMA_BF16(d0, d1, d2, d3, a0, a1, a2, a3, b0, b1)                     \
    asm volatile("mma.sync.aligned.m16n8k16.row.col.f32.bf16.bf16.f32 "      \
                 "{%0,%1,%2,%3}, {%4,%5,%6,%7}, {%8,%9}, {%0,%1,%2,%3};"     \
                 : "+f"(d0), "+f"(d1), "+f"(d2), "+f"(d3)                    \
                 : "r"(a0), "r"(a1), "r"(a2), "r"(a3), "r"(b0), "r"(b1))

#define CP_ASYNC16(dst, src)                                                 \
    asm volatile("cp.async.cg.shared.global [%0], [%1], 16;"                 \
                 :: "r"(dst), "l"(src))
#define CP_COMMIT() asm volatile("cp.async.commit_group;" ::: "memory")
#define CP_WAIT0()  asm volatile("cp.async.wait_group 0;" ::: "memory")

__device__ __forceinline__ float ldcg_f32(const float* p) {
    float v;
    asm volatile("ld.global.cg.f32 %0, [%1];" : "=f"(v) : "l"(p));
    return v;
}

// ============================================================================
// Kernel 0: convert W1 fp32 -> bf16 hi/lo (padded layout); reset counters.
// ============================================================================
__global__ __launch_bounds__(256) void convW_kernel(const float* __restrict__ W1)
{
    const int idx = blockIdx.x * 256 + threadIdx.x;   // 0..32767
    if (idx < BB) g_scnt[idx] = 0;                    // reset per replay
    const int k = idx >> 7;       // H index 0..255
    const int n = idx & 127;      // A index 0..127
    const float w = W1[idx];
    const __nv_bfloat16 hi = __float2bfloat16(w);
    const float hf = __bfloat162float(hi);
    const __nv_bfloat16 lo = __float2bfloat16(w - hf);
    const int chunk = k >> 6;
    const int kc = k & 63;
    const int pos = (chunk * 128 + n) * PADK + kc;
    g_Bhi[pos] = hi;
    g_Blo[pos] = lo;
}

// ============================================================================
// Kernel 1: scores GEMM (mma.sync bf16 hi/lo split) + fused tanh/W2 epilogue
// + per-batch last-CTA fused entmax (bisection) + support compaction.
// One CTA per 128 tokens; 32 CTAs per batch.
// ============================================================================
#define OFF_AHI   0
#define OFF_ALO   18432
#define OFF_BHI   36864
#define OFF_BLO   55296
#define OFF_B1S   73728
#define OFF_W2S   74240
#define OFF_SRED  74752
#define SMEM_BYTES 75776
// entmax-phase reuse (after GEMM done): zs[4096] at 0, redf at 16384,
// iscan[256] at 16512

__global__ __launch_bounds__(256, 2) void scores_mma_kernel(
    const float* __restrict__ X,    // [NTOK, 256]
    const float* __restrict__ b1,   // [128]
    const float* __restrict__ W2,   // [128]
    const float* __restrict__ b2,   // [1]
    float* __restrict__ weights)    // [B, S] output (tuple elem 1)
{
    extern __shared__ __align__(16) char smem[];
    const uint32_t sb = s2u(smem);
    const int tid = threadIdx.x;
    const int wid = tid >> 5;
    const int lane = tid & 31;
    const int tok0 = blockIdx.x * 128;

    const int wm = (wid >> 1) * 32;   // warp M origin (0,32,64,96)
    const int wn = (wid & 1) * 64;    // warp N origin (0,64)

    if (tid < 128) {
        *(float*)(smem + OFF_B1S + tid * 4) = b1[tid];
        *(float*)(smem + OFF_W2S + tid * 4) = W2[tid];
    }

    float acc[2][8][4];
#pragma unroll
    for (int mi = 0; mi < 2; mi++)
#pragma unroll
        for (int nf = 0; nf < 8; nf++)
#pragma unroll
            for (int i = 0; i < 4; i++) acc[mi][nf][i] = 0.0f;

    const int row  = tid >> 1;      // 0..127 (token row in tile)
    const int half = tid & 1;       // 32-col half of the 64-col chunk
    const float4* Xr = (const float4*)(X + (size_t)(tok0 + row) * HH);
    const uint32_t a_boff = (uint32_t)row * (PADK * 2) + (uint32_t)(half * 64);

    const int grp = lane >> 3;
    const uint32_t a_rowl = (uint32_t)((lane & 7) + (grp & 1) * 8);
    const uint32_t a_kad = (uint32_t)((grp >> 1) * 8) * 2;
    const uint32_t b_rowbase = (uint32_t)((lane & 7) + (grp >> 1) * 8);
    const uint32_t b_kad = (uint32_t)((grp & 1) * 8) * 2;

    float4 v[8];
#pragma unroll
    for (int q = 0; q < 8; q++) v[q] = Xr[half * 8 + q];

    for (int c = 0; c < 4; c++) {
        {
            const char* srch = (const char*)(g_Bhi + c * 128 * PADK);
            const char* srcl = (const char*)(g_Blo + c * 128 * PADK);
#pragma unroll
            for (int i = 0; i < 5; i++) {
                const int idx = tid + i * 256;
                if (idx < 1152) {
                    CP_ASYNC16(sb + OFF_BHI + idx * 16, srch + idx * 16);
                    CP_ASYNC16(sb + OFF_BLO + idx * 16, srcl + idx * 16);
                }
            }
            CP_COMMIT();
        }
        {
#pragma unroll
            for (int q = 0; q < 8; q++) {
                const float4 vv = v[q];
                __nv_bfloat162 h0 = __floats2bfloat162_rn(vv.x, vv.y);
                __nv_bfloat162 h1 = __floats2bfloat162_rn(vv.z, vv.w);
                float rx = vv.x - __bfloat162float(__low2bfloat16(h0));
                float ry = vv.y - __bfloat162float(__high2bfloat16(h0));
                float rz = vv.z - __bfloat162float(__low2bfloat16(h1));
                float rw = vv.w - __bfloat162float(__high2bfloat16(h1));
                __nv_bfloat162 l0 = __floats2bfloat162_rn(rx, ry);
                __nv_bfloat162 l1 = __floats2bfloat162_rn(rz, rw);

                const uint32_t boff = a_boff + (uint32_t)(q * 8);
                uint2 hw, lw;
                hw.x = *(uint32_t*)&h0; hw.y = *(uint32_t*)&h1;
                lw.x = *(uint32_t*)&l0; lw.y = *(uint32_t*)&l1;
                *(uint2*)(smem + OFF_AHI + boff) = hw;
                *(uint2*)(smem + OFF_ALO + boff) = lw;
            }
        }
        if (c < 3) {
#pragma unroll
            for (int q = 0; q < 8; q++) v[q] = Xr[(c + 1) * 16 + half * 8 + q];
        }
        CP_WAIT0();
        __syncthreads();

#pragma unroll
        for (int ks = 0; ks < 4; ks++) {
            const uint32_t k0b = (uint32_t)(ks * 16) * 2;
            uint32_t ah[2][4], al[2][4];
#pragma unroll
            for (int mi = 0; mi < 2; mi++) {
                const uint32_t a_off =
                    ((uint32_t)(wm + mi * 16) + a_rowl) * (PADK * 2) + k0b + a_kad;
                LDSM_X4(ah[mi][0], ah[mi][1], ah[mi][2], ah[mi][3],
                        sb + OFF_AHI + a_off);
                LDSM_X4(al[mi][0], al[mi][1], al[mi][2], al[mi][3],
                        sb + OFF_ALO + a_off);
            }
#pragma unroll
            for (int ng = 0; ng < 4; ng++) {
                const uint32_t b_off =
                    ((uint32_t)(wn + ng * 16) + b_rowbase) * (PADK * 2) + k0b + b_kad;
                uint32_t bh0, bh1, bh2, bh3, bl0, bl1, bl2, bl3;
                LDSM_X4(bh0, bh1, bh2, bh3, sb + OFF_BHI + b_off);
                LDSM_X4(bl0, bl1, bl2, bl3, sb + OFF_BLO + b_off);
#pragma unroll
                for (int mi = 0; mi < 2; mi++) {
                    float* d0 = acc[mi][ng * 2];
                    float* d1 = acc[mi][ng * 2 + 1];
                    MMA_BF16(d0[0], d0[1], d0[2], d0[3],
                             ah[mi][0], ah[mi][1], ah[mi][2], ah[mi][3], bh0, bh1);
                    MMA_BF16(d0[0], d0[1], d0[2], d0[3],
                             ah[mi][0], ah[mi][1], ah[mi][2], ah[mi][3], bl0, bl1);
                    MMA_BF16(d0[0], d0[1], d0[2], d0[3],
                             al[mi][0], al[mi][1], al[mi][2], al[mi][3], bh0, bh1);
                    MMA_BF16(d1[0], d1[1], d1[2], d1[3],
                             ah[mi][0], ah[mi][1], ah[mi][2], ah[mi][3], bh2, bh3);
                    MMA_BF16(d1[0], d1[1], d1[2], d1[3],
                             ah[mi][0], ah[mi][1], ah[mi][2], ah[mi][3], bl2, bl3);
                    MMA_BF16(d1[0], d1[1], d1[2], d1[3],
                             al[mi][0], al[mi][1], al[mi][2], al[mi][3], bh2, bh3);
                }
            }
        }
        __syncthreads();
    }

    // ---- epilogue: tanh dot W2 over warp's 64 cols, then cross-warp add ----
    float* sred = (float*)(smem + OFF_SRED);   // [2][128]
#pragma unroll
    for (int mi = 0; mi < 2; mi++) {
        float s0 = 0.0f, s1 = 0.0f;
#pragma unroll
        for (int nf = 0; nf < 8; nf++) {
            const int c0 = wn + nf * 8 + (lane & 3) * 2;
            const float bb0 = *(const float*)(smem + OFF_B1S + c0 * 4);
            const float bb1v = *(const float*)(smem + OFF_B1S + (c0 + 1) * 4);
            const float ww0 = *(const float*)(smem + OFF_W2S + c0 * 4);
            const float ww1 = *(const float*)(smem + OFF_W2S + (c0 + 1) * 4);
            s0 += tanhf(acc[mi][nf][0] + bb0) * ww0 +
                  tanhf(acc[mi][nf][1] + bb1v) * ww1;
            s1 += tanhf(acc[mi][nf][2] + bb0) * ww0 +
                  tanhf(acc[mi][nf][3] + bb1v) * ww1;
        }
        s0 += __shfl_xor_sync(0xffffffffu, s0, 1);
        s0 += __shfl_xor_sync(0xffffffffu, s0, 2);
        s1 += __shfl_xor_sync(0xffffffffu, s1, 1);
        s1 += __shfl_xor_sync(0xffffffffu, s1, 2);
        if ((lane & 3) == 0) {
            const int r = wm + mi * 16 + (lane >> 2);
            sred[(wid & 1) * 128 + r]     = s0;
            sred[(wid & 1) * 128 + r + 8] = s1;
        }
    }
    __syncthreads();
    if (tid < 128)
        g_scores[tok0 + tid] = sred[tid] + sred[128 + tid] + b2[0];

    // ================= fused per-batch entmax (last CTA of the batch) ======
    const int bat = blockIdx.x >> 5;     // 32 CTAs per batch
    __shared__ int s_lastc;
    __shared__ float s_bc2;
    __threadfence();
    if (tid == 0)
        s_lastc = (atomicAdd(&g_scnt[bat], 1) == 31) ? 1 : 0;
    __syncthreads();
    if (!s_lastc) return;

    // smem reuse (GEMM phase done): zs[4096], redf[8], iscan[256]
    float* zs   = (float*)smem;
    float* redf = (float*)(smem + 16384);
    int*  iscan = (int*)(smem + 16512);

    const float* scb = g_scores + (size_t)bat * SS;

    // load z = score/2 (strided, coalesced, L2 via .cg) + block max
    float m = -1e30f;
    for (int i = tid; i < SS; i += 256) {
        const float vv = 0.5f * ldcg_f32(scb + i);
        zs[i] = vv;
        m = fmaxf(m, vv);
    }
#pragma unroll
    for (int o = 16; o > 0; o >>= 1) m = fmaxf(m, __shfl_xor_sync(0xffffffffu, m, o));
    if (lane == 0) redf[wid] = m;
    __syncthreads();
    if (tid == 0) {
        float t = redf[0];
#pragma unroll
        for (int i = 1; i < 8; i++) t = fmaxf(t, redf[i]);
        s_bc2 = t;
    }
    __syncthreads();
    const float mx = s_bc2;

    // bisection on f(tau)=sum((z-mx-tau)_+^2)-1, root in [-1,0]
    float blo = -1.0f, bhi = 0.0f;
    for (int it = 0; it < 30; it++) {
        const float mid = 0.5f * (blo + bhi);
        const float th = mx + mid;
        float s = 0.0f;
        for (int i = tid; i < SS; i += 256) {
            float d = zs[i] - th;
            d = d > 0.0f ? d : 0.0f;
            s = fmaf(d, d, s);
        }
#pragma unroll
        for (int o = 16; o > 0; o >>= 1) s += __shfl_xor_sync(0xffffffffu, s, o);
        if (lane == 0) redf[wid] = s;
        __syncthreads();
        float tot = redf[0] + redf[1] + redf[2] + redf[3] +
                    redf[4] + redf[5] + redf[6] + redf[7];
        __syncthreads();
        if (tot >= 1.0f) blo = mid; else bhi = mid;
    }
    const float thr = mx + 0.5f * (blo + bhi);

    // weights + index-ordered compaction (thread owns contiguous 16)
    float* wout = weights + (size_t)bat * SS;
    const int base = tid * 16;
    int mycnt = 0;
#pragma unroll
    for (int j = 0; j < 16; j++) {
        float d = zs[base + j] - thr;
        d = d > 0.0f ? d : 0.0f;
        const float w = d * d;
        wout[base + j] = w;
        if (w > 0.0f) mycnt++;
    }
    iscan[tid] = mycnt;
    __syncthreads();
    for (int off = 1; off < 256; off <<= 1) {
        int a = 0;
        if (tid >= off) a = iscan[tid - off];
        __syncthreads();
        iscan[tid] += a;
        __syncthreads();
    }
    int pos = iscan[tid] - mycnt;
#pragma unroll
    for (int j = 0; j < 16; j++) {
        float d = zs[base + j] - thr;
        d = d > 0.0f ? d : 0.0f;
        if (d > 0.0f) {
            g_nzidx[(size_t)bat * SS + pos] = base + j;
            g_nzw[(size_t)bat * SS + pos]   = d * d;
            pos++;
        }
    }
    if (tid == 255) g_nzcnt[bat] = iscan[255];
    if (tid == 0)   g_ctr[bat] = 0;
}

// ============================================================================
// Kernel 3: sparse context partials + last-block fused reduce.
// grid (B, NPART), 256 threads (one per h).
// ============================================================================
__global__ __launch_bounds__(256) void ctx_sparse_kernel(
    const float* __restrict__ X, float* __restrict__ ctx)
{
    const int b = blockIdx.x;
    const int sl = blockIdx.y;
    const int h = threadIdx.x;

    __shared__ int   sidx[576];
    __shared__ float swt[576];
    __shared__ int   s_last;

    const int cnt = g_nzcnt[b];
    const int per = (cnt + NPART - 1) / NPART;
    const int s0 = sl * per;
    int s1 = s0 + per; if (s1 > cnt) s1 = cnt;
    const int n = s1 - s0;

    for (int t = h; t < n; t += 256) {
        sidx[t] = g_nzidx[(size_t)b * SS + s0 + t];
        swt[t]  = g_nzw[(size_t)b * SS + s0 + t];
    }
    __syncthreads();

    const float* Xb = X + (size_t)b * SS * HH;
    float acc = 0.0f;
    int i = 0;
    for (; i + 8 <= n; i += 8) {
        float x0 = Xb[(size_t)sidx[i]     * HH + h];
        float x1 = Xb[(size_t)sidx[i + 1] * HH + h];
        float x2 = Xb[(size_t)sidx[i + 2] * HH + h];
        float x3 = Xb[(size_t)sidx[i + 3] * HH + h];
        float x4 = Xb[(size_t)sidx[i + 4] * HH + h];
        float x5 = Xb[(size_t)sidx[i + 5] * HH + h];
        float x6 = Xb[(size_t)sidx[i + 6] * HH + h];
        float x7 = Xb[(size_t)sidx[i + 7] * HH + h];
        acc = fmaf(x0, swt[i],     acc);
        acc = fmaf(x1, swt[i + 1], acc);
        acc = fmaf(x2, swt[i + 2], acc);
        acc = fmaf(x3, swt[i + 3], acc);
        acc = fmaf(x4, swt[i + 4], acc);
        acc = fmaf(x5, swt[i + 5], acc);
        acc = fmaf(x6, swt[i + 6], acc);
        acc = fmaf(x7, swt[i + 7], acc);
    }
    for (; i < n; i++)
        acc = fmaf(Xb[(size_t)sidx[i] * HH + h], swt[i], acc);

    g_partial[((size_t)b * NPART + sl) * HH + h] = acc;

    __threadfence();
    __syncthreads();
    if (h == 0) {
        const int old = atomicAdd(&g_ctr[b], 1);
        s_last = (old == NPART - 1) ? 1 : 0;
    }
    __syncthreads();
    if (s_last) {
        float s = 0.0f;
#pragma unroll
        for (int c = 0; c < NPART; c++)
            s += ldcg_f32(&g_partial[((size_t)b * NPART + c) * HH + h]);
        ctx[(size_t)b * HH + h] = s;
    }
}

// ============================================================================
extern "C" void kernel_launch(void* const* d_in, const int* in_sizes, int n_in,
                              void* d_out, int out_size)
{
    const float* X  = (const float*)d_in[0];   // [64,4096,256]
    const float* W1 = (const float*)d_in[1];   // [256,128]
    const float* b1 = (const float*)d_in[2];   // [128]
    const float* W2 = (const float*)d_in[3];   // [128,1]
    const float* b2 = (const float*)d_in[4];   // [1]

    float* out = (float*)d_out;
    float* ctx = out;                 // [64,256]  (tuple elem 0)
    float* wts = out + BB * HH;       // [64,4096] (tuple elem 1)

    cudaFuncSetAttribute(scores_mma_kernel,
                         cudaFuncAttributeMaxDynamicSharedMemorySize, SMEM_BYTES);

    convW_kernel<<<128, 256>>>(W1);
    scores_mma_kernel<<<NTOK / 128, 256, SMEM_BYTES>>>(X, b1, W2, b2, wts);
    ctx_sparse_kernel<<<dim3(BB, NPART), 256>>>(X, ctx);
}

// round 11
// speedup vs baseline: 1.0897x; 1.0897x over previous
#include <cuda_runtime.h>
#include <cuda_bf16.h>
#include <cstdint>

// Problem constants
#define BB 64
#define SS 4096
#define HH 256
#define AA 128
#define NTOK (BB * SS)          // 262144 tokens

#define PADK 72                 // bf16 elems per smem row (144B, conflict-free)
#define NPART 8                 // context partial slices per batch

// ---------------- scratch (device globals; no allocation allowed) ----------
__device__ float g_scores[NTOK];                    // [B,S] pre-entmax scores
__device__ float g_partial[BB * NPART * HH];        // context partials
__device__ int   g_nzidx[NTOK];                     // compacted support idx
__device__ float g_nzw[NTOK];                       // compacted support w
__device__ int   g_nzcnt[BB];                       // support count per batch
__device__ int   g_ctr[BB];                         // ctx slice arrival counter
// W1 pre-converted to bf16 hi/lo, padded chunk layout: [4 chunks][128 n][72]
__device__ __nv_bfloat16 g_Bhi[4 * 128 * PADK];
__device__ __nv_bfloat16 g_Blo[4 * 128 * PADK];

// ---------------- PTX helpers ----------------------------------------------
__device__ __forceinline__ uint32_t s2u(const void* p) {
    uint32_t a;
    asm("{ .reg .u64 t; cvta.to.shared.u64 t, %1; cvt.u32.u64 %0, t; }"
        : "=r"(a) : "l"(p));
    return a;
}

#define LDSM_X4(r0, r1, r2, r3, addr)                                        \
    asm volatile("ldmatrix.sync.aligned.m8n8.x4.shared.b16 {%0,%1,%2,%3}, [%4];" \
                 : "=r"(r0), "=r"(r1), "=r"(r2), "=r"(r3) : "r"(addr))

#define MMA_BF16(d0, d1, d2, d3, a0, a1, a2, a3, b0, b1)                     \
    asm volatile("mma.sync.aligned.m16n8k16.row.col.f32.bf16.bf16.f32 "      \
                 "{%0,%1,%2,%3}, {%4,%5,%6,%7}, {%8,%9}, {%0,%1,%2,%3};"     \
                 : "+f"(d0), "+f"(d1), "+f"(d2), "+f"(d3)                    \
                 : "r"(a0), "r"(a1), "r"(a2), "r"(a3), "r"(b0), "r"(b1))

#define CP_ASYNC16(dst, src)                                                 \
    asm volatile("cp.async.cg.shared.global [%0], [%1], 16;"                 \
                 :: "r"(dst), "l"(src))
#define CP_COMMIT() asm volatile("cp.async.commit_group;" ::: "memory")
#define CP_WAIT0()  asm volatile("cp.async.wait_group 0;" ::: "memory")

__device__ __forceinline__ float ldcg_f32(const float* p) {
    float v;
    asm volatile("ld.global.cg.f32 %0, [%1];" : "=f"(v) : "l"(p));
    return v;
}

// ============================================================================
// Kernel 0: convert W1 [256,128] fp32 -> bf16 hi/lo, padded chunk layout.
// ============================================================================
__global__ __launch_bounds__(256) void convW_kernel(const float* __restrict__ W1)
{
    const int idx = blockIdx.x * 256 + threadIdx.x;   // 0..32767
    const int k = idx >> 7;       // H index 0..255
    const int n = idx & 127;      // A index 0..127
    const float w = W1[idx];
    const __nv_bfloat16 hi = __float2bfloat16(w);
    const float hf = __bfloat162float(hi);
    const __nv_bfloat16 lo = __float2bfloat16(w - hf);
    const int chunk = k >> 6;
    const int kc = k & 63;
    const int pos = (chunk * 128 + n) * PADK + kc;
    g_Bhi[pos] = hi;
    g_Blo[pos] = lo;
}

// ============================================================================
// Kernel 1: scores GEMM via mma.sync bf16 hi/lo split + fused tanh/W2
// epilogue. One CTA per 128 tokens; 8 warps, warp tile m32 x n64.
// (unchanged — at the legacy-HMMA rate floor)
// ============================================================================
#define OFF_AHI   0
#define OFF_ALO   18432
#define OFF_BHI   36864
#define OFF_BLO   55296
#define OFF_B1S   73728
#define OFF_W2S   74240
#define OFF_SRED  74752
#define SMEM_BYTES 75776

__global__ __launch_bounds__(256, 2) void scores_mma_kernel(
    const float* __restrict__ X,    // [NTOK, 256]
    const float* __restrict__ b1,   // [128]
    const float* __restrict__ W2,   // [128]
    const float* __restrict__ b2)   // [1]
{
    extern __shared__ __align__(16) char smem[];
    const uint32_t sb = s2u(smem);
    const int tid = threadIdx.x;
    const int wid = tid >> 5;
    const int lane = tid & 31;
    const int tok0 = blockIdx.x * 128;

    const int wm = (wid >> 1) * 32;   // warp M origin (0,32,64,96)
    const int wn = (wid & 1) * 64;    // warp N origin (0,64)

    if (tid < 128) {
        *(float*)(smem + OFF_B1S + tid * 4) = b1[tid];
        *(float*)(smem + OFF_W2S + tid * 4) = W2[tid];
    }

    float acc[2][8][4];
#pragma unroll
    for (int mi = 0; mi < 2; mi++)
#pragma unroll
        for (int nf = 0; nf < 8; nf++)
#pragma unroll
            for (int i = 0; i < 4; i++) acc[mi][nf][i] = 0.0f;

    const int row  = tid >> 1;      // 0..127 (token row in tile)
    const int half = tid & 1;       // 32-col half of the 64-col chunk
    const float4* Xr = (const float4*)(X + (size_t)(tok0 + row) * HH);
    const uint32_t a_boff = (uint32_t)row * (PADK * 2) + (uint32_t)(half * 64);

    const int grp = lane >> 3;
    const uint32_t a_rowl = (uint32_t)((lane & 7) + (grp & 1) * 8);
    const uint32_t a_kad = (uint32_t)((grp >> 1) * 8) * 2;
    const uint32_t b_rowbase = (uint32_t)((lane & 7) + (grp >> 1) * 8);
    const uint32_t b_kad = (uint32_t)((grp & 1) * 8) * 2;

    float4 v[8];
#pragma unroll
    for (int q = 0; q < 8; q++) v[q] = Xr[half * 8 + q];

    for (int c = 0; c < 4; c++) {
        {
            const char* srch = (const char*)(g_Bhi + c * 128 * PADK);
            const char* srcl = (const char*)(g_Blo + c * 128 * PADK);
#pragma unroll
            for (int i = 0; i < 5; i++) {
                const int idx = tid + i * 256;
                if (idx < 1152) {
                    CP_ASYNC16(sb + OFF_BHI + idx * 16, srch + idx * 16);
                    CP_ASYNC16(sb + OFF_BLO + idx * 16, srcl + idx * 16);
                }
            }
            CP_COMMIT();
        }
        {
#pragma unroll
            for (int q = 0; q < 8; q++) {
                const float4 vv = v[q];
                __nv_bfloat162 h0 = __floats2bfloat162_rn(vv.x, vv.y);
                __nv_bfloat162 h1 = __floats2bfloat162_rn(vv.z, vv.w);
                float rx = vv.x - __bfloat162float(__low2bfloat16(h0));
                float ry = vv.y - __bfloat162float(__high2bfloat16(h0));
                float rz = vv.z - __bfloat162float(__low2bfloat16(h1));
                float rw = vv.w - __bfloat162float(__high2bfloat16(h1));
                __nv_bfloat162 l0 = __floats2bfloat162_rn(rx, ry);
                __nv_bfloat162 l1 = __floats2bfloat162_rn(rz, rw);

                const uint32_t boff = a_boff + (uint32_t)(q * 8);
                uint2 hw, lw;
                hw.x = *(uint32_t*)&h0; hw.y = *(uint32_t*)&h1;
                lw.x = *(uint32_t*)&l0; lw.y = *(uint32_t*)&l1;
                *(uint2*)(smem + OFF_AHI + boff) = hw;
                *(uint2*)(smem + OFF_ALO + boff) = lw;
            }
        }
        if (c < 3) {
#pragma unroll
            for (int q = 0; q < 8; q++) v[q] = Xr[(c + 1) * 16 + half * 8 + q];
        }
        CP_WAIT0();
        __syncthreads();

#pragma unroll
        for (int ks = 0; ks < 4; ks++) {
            const uint32_t k0b = (uint32_t)(ks * 16) * 2;
            uint32_t ah[2][4], al[2][4];
#pragma unroll
            for (int mi = 0; mi < 2; mi++) {
                const uint32_t a_off =
                    ((uint32_t)(wm + mi * 16) + a_rowl) * (PADK * 2) + k0b + a_kad;
                LDSM_X4(ah[mi][0], ah[mi][1], ah[mi][2], ah[mi][3],
                        sb + OFF_AHI + a_off);
                LDSM_X4(al[mi][0], al[mi][1], al[mi][2], al[mi][3],
                        sb + OFF_ALO + a_off);
            }
#pragma unroll
            for (int ng = 0; ng < 4; ng++) {
                const uint32_t b_off =
                    ((uint32_t)(wn + ng * 16) + b_rowbase) * (PADK * 2) + k0b + b_kad;
                uint32_t bh0, bh1, bh2, bh3, bl0, bl1, bl2, bl3;
                LDSM_X4(bh0, bh1, bh2, bh3, sb + OFF_BHI + b_off);
                LDSM_X4(bl0, bl1, bl2, bl3, sb + OFF_BLO + b_off);
#pragma unroll
                for (int mi = 0; mi < 2; mi++) {
                    float* d0 = acc[mi][ng * 2];
                    float* d1 = acc[mi][ng * 2 + 1];
                    MMA_BF16(d0[0], d0[1], d0[2], d0[3],
                             ah[mi][0], ah[mi][1], ah[mi][2], ah[mi][3], bh0, bh1);
                    MMA_BF16(d0[0], d0[1], d0[2], d0[3],
                             ah[mi][0], ah[mi][1], ah[mi][2], ah[mi][3], bl0, bl1);
                    MMA_BF16(d0[0], d0[1], d0[2], d0[3],
                             al[mi][0], al[mi][1], al[mi][2], al[mi][3], bh0, bh1);
                    MMA_BF16(d1[0], d1[1], d1[2], d1[3],
                             ah[mi][0], ah[mi][1], ah[mi][2], ah[mi][3], bh2, bh3);
                    MMA_BF16(d1[0], d1[1], d1[2], d1[3],
                             ah[mi][0], ah[mi][1], ah[mi][2], ah[mi][3], bl2, bl3);
                    MMA_BF16(d1[0], d1[1], d1[2], d1[3],
                             al[mi][0], al[mi][1], al[mi][2], al[mi][3], bh2, bh3);
                }
            }
        }
        __syncthreads();
    }

    // ---- epilogue: tanh dot W2 over warp's 64 cols, then cross-warp add ----
    float* sred = (float*)(smem + OFF_SRED);   // [2][128]
#pragma unroll
    for (int mi = 0; mi < 2; mi++) {
        float s0 = 0.0f, s1 = 0.0f;
#pragma unroll
        for (int nf = 0; nf < 8; nf++) {
            const int c0 = wn + nf * 8 + (lane & 3) * 2;
            const float bb0 = *(const float*)(smem + OFF_B1S + c0 * 4);
            const float bb1v = *(const float*)(smem + OFF_B1S + (c0 + 1) * 4);
            const float ww0 = *(const float*)(smem + OFF_W2S + c0 * 4);
            const float ww1 = *(const float*)(smem + OFF_W2S + (c0 + 1) * 4);
            s0 += tanhf(acc[mi][nf][0] + bb0) * ww0 +
                  tanhf(acc[mi][nf][1] + bb1v) * ww1;
            s1 += tanhf(acc[mi][nf][2] + bb0) * ww0 +
                  tanhf(acc[mi][nf][3] + bb1v) * ww1;
        }
        s0 += __shfl_xor_sync(0xffffffffu, s0, 1);
        s0 += __shfl_xor_sync(0xffffffffu, s0, 2);
        s1 += __shfl_xor_sync(0xffffffffu, s1, 1);
        s1 += __shfl_xor_sync(0xffffffffu, s1, 2);
        if ((lane & 3) == 0) {
            const int r = wm + mi * 16 + (lane >> 2);
            sred[(wid & 1) * 128 + r]     = s0;
            sred[(wid & 1) * 128 + r + 8] = s1;
        }
    }
    __syncthreads();
    if (tid < 128)
        g_scores[tok0 + tid] = sred[tid] + sred[128 + tid] + b2[0];
}

// ============================================================================
// Kernel 2: entmax-1.5 per batch row via fixed-count bisection (no sort)
// + deterministic support compaction to global. Also resets g_ctr[b].
// ============================================================================
__global__ __launch_bounds__(512) void entmax_kernel(float* __restrict__ weights)
{
    const int b = blockIdx.x;
    const int tid = threadIdx.x;
    const int wid = tid >> 5;
    const int lane = tid & 31;

    __shared__ float red[16];
    __shared__ float s_bc;
    __shared__ int iscan[512];

    if (tid == 0) g_ctr[b] = 0;     // reset ctx arrival counter each replay

    const float* sc = g_scores + (size_t)b * SS;
    const int base = tid * 8;

    float z[8];
    {
        const float4 p0 = ((const float4*)sc)[tid * 2];
        const float4 p1 = ((const float4*)sc)[tid * 2 + 1];
        z[0] = 0.5f * p0.x; z[1] = 0.5f * p0.y;
        z[2] = 0.5f * p0.z; z[3] = 0.5f * p0.w;
        z[4] = 0.5f * p1.x; z[5] = 0.5f * p1.y;
        z[6] = 0.5f * p1.z; z[7] = 0.5f * p1.w;
    }

    float m = z[0];
#pragma unroll
    for (int j = 1; j < 8; j++) m = fmaxf(m, z[j]);
#pragma unroll
    for (int o = 16; o > 0; o >>= 1) m = fmaxf(m, __shfl_xor_sync(0xffffffffu, m, o));
    if (lane == 0) red[wid] = m;
    __syncthreads();
    if (tid == 0) {
        float t = red[0];
#pragma unroll
        for (int i = 1; i < 16; i++) t = fmaxf(t, red[i]);
        s_bc = t;
    }
    __syncthreads();
    const float mx = s_bc;
#pragma unroll
    for (int j = 0; j < 8; j++) z[j] -= mx;

    float lo = -1.0f, hi = 0.0f;
    for (int it = 0; it < 30; it++) {
        const float mid = 0.5f * (lo + hi);
        float s = 0.0f;
#pragma unroll
        for (int j = 0; j < 8; j++) {
            float d = z[j] - mid;
            d = d > 0.0f ? d : 0.0f;
            s = fmaf(d, d, s);
        }
#pragma unroll
        for (int o = 16; o > 0; o >>= 1) s += __shfl_xor_sync(0xffffffffu, s, o);
        if (lane == 0) red[wid] = s;
        __syncthreads();
        float tot = 0.0f;
#pragma unroll
        for (int i = 0; i < 16; i++) tot += red[i];
        __syncthreads();
        if (tot >= 1.0f) lo = mid; else hi = mid;
    }
    const float tau = 0.5f * (lo + hi);

    float* wout = weights + (size_t)b * SS;
    float wv[8];
    int mycnt = 0;
#pragma unroll
    for (int j = 0; j < 8; j++) {
        float d = z[j] - tau;
        d = d > 0.0f ? d : 0.0f;
        const float w = d * d;
        wv[j] = w;
        wout[base + j] = w;
        if (w > 0.0f) mycnt++;
    }
    iscan[tid] = mycnt;
    __syncthreads();
    for (int off = 1; off < 512; off <<= 1) {
        int a = 0;
        if (tid >= off) a = iscan[tid - off];
        __syncthreads();
        iscan[tid] += a;
        __syncthreads();
    }
    int pos = iscan[tid] - mycnt;
#pragma unroll
    for (int j = 0; j < 8; j++) {
        if (wv[j] > 0.0f) {
            g_nzidx[(size_t)b * SS + pos] = base + j;
            g_nzw[(size_t)b * SS + pos]   = wv[j];
            pos++;
        }
    }
    if (tid == 511) g_nzcnt[b] = iscan[511];
}

// ============================================================================
// Kernel 3: sparse context partials + last-block fused reduce.
// grid (B, NPART), 256 threads (one per h). Deep (16) unroll for MLP.
// ============================================================================
__global__ __launch_bounds__(256) void ctx_sparse_kernel(
    const float* __restrict__ X, float* __restrict__ ctx)
{
    const int b = blockIdx.x;
    const int sl = blockIdx.y;
    const int h = threadIdx.x;

    __shared__ int   sidx[576];
    __shared__ float swt[576];
    __shared__ int   s_last;

    const int cnt = g_nzcnt[b];
    const int per = (cnt + NPART - 1) / NPART;
    const int s0 = sl * per;
    int s1 = s0 + per; if (s1 > cnt) s1 = cnt;
    const int n = s1 - s0;

    for (int t = h; t < n; t += 256) {
        sidx[t] = g_nzidx[(size_t)b * SS + s0 + t];
        swt[t]  = g_nzw[(size_t)b * SS + s0 + t];
    }
    __syncthreads();

    const float* Xb = X + (size_t)b * SS * HH;
    float acc = 0.0f;
    int i = 0;
    // 16-deep batches: all loads issued before any consumption (MLP=16)
    for (; i + 16 <= n; i += 16) {
        float x[16];
#pragma unroll
        for (int j = 0; j < 16; j++)
            x[j] = Xb[(size_t)sidx[i + j] * HH + h];
#pragma unroll
        for (int j = 0; j < 16; j++)
            acc = fmaf(x[j], swt[i + j], acc);
    }
    for (; i + 8 <= n; i += 8) {
        float x[8];
#pragma unroll
        for (int j = 0; j < 8; j++)
            x[j] = Xb[(size_t)sidx[i + j] * HH + h];
#pragma unroll
        for (int j = 0; j < 8; j++)
            acc = fmaf(x[j], swt[i + j], acc);
    }
    for (; i < n; i++)
        acc = fmaf(Xb[(size_t)sidx[i] * HH + h], swt[i], acc);

    g_partial[((size_t)b * NPART + sl) * HH + h] = acc;

    // last-arriving block for this batch reduces all NPART partials
    __threadfence();
    __syncthreads();
    if (h == 0) {
        const int old = atomicAdd(&g_ctr[b], 1);
        s_last = (old == NPART - 1) ? 1 : 0;
    }
    __syncthreads();
    if (s_last) {
        float s = 0.0f;
#pragma unroll
        for (int c = 0; c < NPART; c++)
            s += ldcg_f32(&g_partial[((size_t)b * NPART + c) * HH + h]);
        ctx[(size_t)b * HH + h] = s;
    }
}

// ============================================================================
extern "C" void kernel_launch(void* const* d_in, const int* in_sizes, int n_in,
                              void* d_out, int out_size)
{
    const float* X  = (const float*)d_in[0];   // [64,4096,256]
    const float* W1 = (const float*)d_in[1];   // [256,128]
    const float* b1 = (const float*)d_in[2];   // [128]
    const float* W2 = (const float*)d_in[3];   // [128,1]
    const float* b2 = (const float*)d_in[4];   // [1]

    float* out = (float*)d_out;
    float* ctx = out;                 // [64,256]  (tuple elem 0)
    float* wts = out + BB * HH;       // [64,4096] (tuple elem 1)

    cudaFuncSetAttribute(scores_mma_kernel,
                         cudaFuncAttributeMaxDynamicSharedMemorySize, SMEM_BYTES);

    convW_kernel<<<128, 256>>>(W1);
    scores_mma_kernel<<<NTOK / 128, 256, SMEM_BYTES>>>(X, b1, W2, b2);
    entmax_kernel<<<BB, 512>>>(wts);
    ctx_sparse_kernel<<<dim3(BB, NPART), 256>>>(X, ctx);
}

// round 12
// speedup vs baseline: 1.3782x; 1.2648x over previous
#include <cuda_runtime.h>
#include <cuda_fp16.h>
#include <cstdint>

// Problem constants
#define BB 64
#define SS 4096
#define HH 256
#define AA 128
#define NTOK (BB * SS)          // 262144 tokens

#define PADK 72                 // fp16 elems per smem row (144B, conflict-free)
#define NPART 8                 // context partial slices per batch

// ---------------- scratch (device globals; no allocation allowed) ----------
__device__ float g_scores[NTOK];                    // [B,S] pre-entmax scores
__device__ float g_partial[BB * NPART * HH];        // context partials
__device__ int   g_nzidx[NTOK];                     // compacted support idx
__device__ float g_nzw[NTOK];                       // compacted support w
__device__ int   g_nzcnt[BB];                       // support count per batch
__device__ int   g_ctr[BB];                         // ctx slice arrival counter
// W1 pre-converted to fp16 hi/lo, padded chunk layout: [4 chunks][128 n][72]
__device__ __half g_Bhi[4 * 128 * PADK];
__device__ __half g_Blo[4 * 128 * PADK];

// ---------------- PTX helpers ----------------------------------------------
__device__ __forceinline__ uint32_t s2u(const void* p) {
    uint32_t a;
    asm("{ .reg .u64 t; cvta.to.shared.u64 t, %1; cvt.u32.u64 %0, t; }"
        : "=r"(a) : "l"(p));
    return a;
}

#define LDSM_X4(r0, r1, r2, r3, addr)                                        \
    asm volatile("ldmatrix.sync.aligned.m8n8.x4.shared.b16 {%0,%1,%2,%3}, [%4];" \
                 : "=r"(r0), "=r"(r1), "=r"(r2), "=r"(r3) : "r"(addr))

#define MMA_FP16(d0, d1, d2, d3, a0, a1, a2, a3, b0, b1)                     \
    asm volatile("mma.sync.aligned.m16n8k16.row.col.f32.f16.f16.f32 "       \
                 "{%0,%1,%2,%3}, {%4,%5,%6,%7}, {%8,%9}, {%0,%1,%2,%3};"     \
                 : "+f"(d0), "+f"(d1), "+f"(d2), "+f"(d3)                    \
                 : "r"(a0), "r"(a1), "r"(a2), "r"(a3), "r"(b0), "r"(b1))

#define CP_ASYNC16(dst, src)                                                 \
    asm volatile("cp.async.cg.shared.global [%0], [%1], 16;"                 \
                 :: "r"(dst), "l"(src))
#define CP_COMMIT() asm volatile("cp.async.commit_group;" ::: "memory")
#define CP_WAIT0()  asm volatile("cp.async.wait_group 0;" ::: "memory")

__device__ __forceinline__ float ldcg_f32(const float* p) {
    float v;
    asm volatile("ld.global.cg.f32 %0, [%1];" : "=f"(v) : "l"(p));
    return v;
}

// ============================================================================
// Kernel 0: convert W1 [256,128] fp32 -> fp16 hi/lo, padded chunk layout.
// W1 = hi + lo exact to ~2^-22.
// ============================================================================
__global__ __launch_bounds__(256) void convW_kernel(const float* __restrict__ W1)
{
    const int idx = blockIdx.x * 256 + threadIdx.x;   // 0..32767
    const int k = idx >> 7;       // H index 0..255
    const int n = idx & 127;      // A index 0..127
    const float w = W1[idx];
    const __half hi = __float2half_rn(w);
    const float hf = __half2float(hi);
    const __half lo = __float2half_rn(w - hf);
    const int chunk = k >> 6;
    const int kc = k & 63;
    const int pos = (chunk * 128 + n) * PADK + kc;
    g_Bhi[pos] = hi;
    g_Blo[pos] = lo;
}

// ============================================================================
// Kernel 1: scores GEMM via mma.sync fp16 asymmetric split:
//   D = Xh * (Whi + Wlo),  Xh = RN_fp16(X).
// One CTA per 128 tokens; 8 warps, warp tile m32 x n64. 32 MMA/warp/kstep.
// ============================================================================
#define OFF_A     0
#define OFF_BHI   18432
#define OFF_BLO   36864
#define OFF_B1S   55296
#define OFF_W2S   55808
#define OFF_SRED  56320
#define SMEM_BYTES 57344

__global__ __launch_bounds__(256, 2) void scores_mma_kernel(
    const float* __restrict__ X,    // [NTOK, 256]
    const float* __restrict__ b1,   // [128]
    const float* __restrict__ W2,   // [128]
    const float* __restrict__ b2)   // [1]
{
    extern __shared__ __align__(16) char smem[];
    const uint32_t sb = s2u(smem);
    const int tid = threadIdx.x;
    const int wid = tid >> 5;
    const int lane = tid & 31;
    const int tok0 = blockIdx.x * 128;

    const int wm = (wid >> 1) * 32;   // warp M origin (0,32,64,96)
    const int wn = (wid & 1) * 64;    // warp N origin (0,64)

    if (tid < 128) {
        *(float*)(smem + OFF_B1S + tid * 4) = b1[tid];
        *(float*)(smem + OFF_W2S + tid * 4) = W2[tid];
    }

    float acc[2][8][4];
#pragma unroll
    for (int mi = 0; mi < 2; mi++)
#pragma unroll
        for (int nf = 0; nf < 8; nf++)
#pragma unroll
            for (int i = 0; i < 4; i++) acc[mi][nf][i] = 0.0f;

    const int row  = tid >> 1;      // 0..127 (token row in tile)
    const int half = tid & 1;       // 32-col half of the 64-col chunk
    const float4* Xr = (const float4*)(X + (size_t)(tok0 + row) * HH);
    const uint32_t a_boff = (uint32_t)row * (PADK * 2) + (uint32_t)(half * 64);

    const int grp = lane >> 3;
    const uint32_t a_rowl = (uint32_t)((lane & 7) + (grp & 1) * 8);
    const uint32_t a_kad = (uint32_t)((grp >> 1) * 8) * 2;
    const uint32_t b_rowbase = (uint32_t)((lane & 7) + (grp >> 1) * 8);
    const uint32_t b_kad = (uint32_t)((grp & 1) * 8) * 2;

    float4 v[8];
#pragma unroll
    for (int q = 0; q < 8; q++) v[q] = Xr[half * 8 + q];

    for (int c = 0; c < 4; c++) {
        // ---- B chunk via cp.async (hi + lo, 18432B each) ----
        {
            const char* srch = (const char*)(g_Bhi + c * 128 * PADK);
            const char* srcl = (const char*)(g_Blo + c * 128 * PADK);
#pragma unroll
            for (int i = 0; i < 5; i++) {
                const int idx = tid + i * 256;
                if (idx < 1152) {
                    CP_ASYNC16(sb + OFF_BHI + idx * 16, srch + idx * 16);
                    CP_ASYNC16(sb + OFF_BLO + idx * 16, srcl + idx * 16);
                }
            }
            CP_COMMIT();
        }
        // ---- convert staged A chunk -> fp16 (single tile) ----
        {
#pragma unroll
            for (int q = 0; q < 8; q++) {
                const float4 vv = v[q];
                const __half2 h0 = __floats2half2_rn(vv.x, vv.y);
                const __half2 h1 = __floats2half2_rn(vv.z, vv.w);
                uint2 hw;
                hw.x = *(const uint32_t*)&h0;
                hw.y = *(const uint32_t*)&h1;
                *(uint2*)(smem + OFF_A + a_boff + (uint32_t)(q * 8)) = hw;
            }
        }
        if (c < 3) {
#pragma unroll
            for (int q = 0; q < 8; q++) v[q] = Xr[(c + 1) * 16 + half * 8 + q];
        }
        CP_WAIT0();
        __syncthreads();

        // ---- 4 k-steps of 16, 32 MMA each ----
#pragma unroll
        for (int ks = 0; ks < 4; ks++) {
            const uint32_t k0b = (uint32_t)(ks * 16) * 2;
            uint32_t ah[2][4];
#pragma unroll
            for (int mi = 0; mi < 2; mi++) {
                const uint32_t a_off =
                    ((uint32_t)(wm + mi * 16) + a_rowl) * (PADK * 2) + k0b + a_kad;
                LDSM_X4(ah[mi][0], ah[mi][1], ah[mi][2], ah[mi][3],
                        sb + OFF_A + a_off);
            }
#pragma unroll
            for (int ng = 0; ng < 4; ng++) {
                const uint32_t b_off =
                    ((uint32_t)(wn + ng * 16) + b_rowbase) * (PADK * 2) + k0b + b_kad;
                uint32_t bh0, bh1, bh2, bh3, bl0, bl1, bl2, bl3;
                LDSM_X4(bh0, bh1, bh2, bh3, sb + OFF_BHI + b_off);
                LDSM_X4(bl0, bl1, bl2, bl3, sb + OFF_BLO + b_off);
#pragma unroll
                for (int mi = 0; mi < 2; mi++) {
                    float* d0 = acc[mi][ng * 2];
                    float* d1 = acc[mi][ng * 2 + 1];
                    MMA_FP16(d0[0], d0[1], d0[2], d0[3],
                             ah[mi][0], ah[mi][1], ah[mi][2], ah[mi][3], bh0, bh1);
                    MMA_FP16(d0[0], d0[1], d0[2], d0[3],
                             ah[mi][0], ah[mi][1], ah[mi][2], ah[mi][3], bl0, bl1);
                    MMA_FP16(d1[0], d1[1], d1[2], d1[3],
                             ah[mi][0], ah[mi][1], ah[mi][2], ah[mi][3], bh2, bh3);
                    MMA_FP16(d1[0], d1[1], d1[2], d1[3],
                             ah[mi][0], ah[mi][1], ah[mi][2], ah[mi][3], bl2, bl3);
                }
            }
        }
        __syncthreads();
    }

    // ---- epilogue: tanh dot W2 over warp's 64 cols, then cross-warp add ----
    float* sred = (float*)(smem + OFF_SRED);   // [2][128]
#pragma unroll
    for (int mi = 0; mi < 2; mi++) {
        float s0 = 0.0f, s1 = 0.0f;
#pragma unroll
        for (int nf = 0; nf < 8; nf++) {
            const int c0 = wn + nf * 8 + (lane & 3) * 2;
            const float bb0 = *(const float*)(smem + OFF_B1S + c0 * 4);
            const float bb1v = *(const float*)(smem + OFF_B1S + (c0 + 1) * 4);
            const float ww0 = *(const float*)(smem + OFF_W2S + c0 * 4);
            const float ww1 = *(const float*)(smem + OFF_W2S + (c0 + 1) * 4);
            s0 += tanhf(acc[mi][nf][0] + bb0) * ww0 +
                  tanhf(acc[mi][nf][1] + bb1v) * ww1;
            s1 += tanhf(acc[mi][nf][2] + bb0) * ww0 +
                  tanhf(acc[mi][nf][3] + bb1v) * ww1;
        }
        s0 += __shfl_xor_sync(0xffffffffu, s0, 1);
        s0 += __shfl_xor_sync(0xffffffffu, s0, 2);
        s1 += __shfl_xor_sync(0xffffffffu, s1, 1);
        s1 += __shfl_xor_sync(0xffffffffu, s1, 2);
        if ((lane & 3) == 0) {
            const int r = wm + mi * 16 + (lane >> 2);
            sred[(wid & 1) * 128 + r]     = s0;
            sred[(wid & 1) * 128 + r + 8] = s1;
        }
    }
    __syncthreads();
    if (tid < 128)
        g_scores[tok0 + tid] = sred[tid] + sred[128 + tid] + b2[0];
}

// ============================================================================
// Kernel 2: entmax-1.5 per batch row via fixed-count bisection (no sort)
// + deterministic support compaction to global. Also resets g_ctr[b].
// ============================================================================
__global__ __launch_bounds__(512) void entmax_kernel(float* __restrict__ weights)
{
    const int b = blockIdx.x;
    const int tid = threadIdx.x;
    const int wid = tid >> 5;
    const int lane = tid & 31;

    __shared__ float red[16];
    __shared__ float s_bc;
    __shared__ int iscan[512];

    if (tid == 0) g_ctr[b] = 0;     // reset ctx arrival counter each replay

    const float* sc = g_scores + (size_t)b * SS;
    const int base = tid * 8;

    float z[8];
    {
        const float4 p0 = ((const float4*)sc)[tid * 2];
        const float4 p1 = ((const float4*)sc)[tid * 2 + 1];
        z[0] = 0.5f * p0.x; z[1] = 0.5f * p0.y;
        z[2] = 0.5f * p0.z; z[3] = 0.5f * p0.w;
        z[4] = 0.5f * p1.x; z[5] = 0.5f * p1.y;
        z[6] = 0.5f * p1.z; z[7] = 0.5f * p1.w;
    }

    float m = z[0];
#pragma unroll
    for (int j = 1; j < 8; j++) m = fmaxf(m, z[j]);
#pragma unroll
    for (int o = 16; o > 0; o >>= 1) m = fmaxf(m, __shfl_xor_sync(0xffffffffu, m, o));
    if (lane == 0) red[wid] = m;
    __syncthreads();
    if (tid == 0) {
        float t = red[0];
#pragma unroll
        for (int i = 1; i < 16; i++) t = fmaxf(t, red[i]);
        s_bc = t;
    }
    __syncthreads();
    const float mx = s_bc;
#pragma unroll
    for (int j = 0; j < 8; j++) z[j] -= mx;

    float lo = -1.0f, hi = 0.0f;
    for (int it = 0; it < 30; it++) {
        const float mid = 0.5f * (lo + hi);
        float s = 0.0f;
#pragma unroll
        for (int j = 0; j < 8; j++) {
            float d = z[j] - mid;
            d = d > 0.0f ? d : 0.0f;
            s = fmaf(d, d, s);
        }
#pragma unroll
        for (int o = 16; o > 0; o >>= 1) s += __shfl_xor_sync(0xffffffffu, s, o);
        if (lane == 0) red[wid] = s;
        __syncthreads();
        float tot = 0.0f;
#pragma unroll
        for (int i = 0; i < 16; i++) tot += red[i];
        __syncthreads();
        if (tot >= 1.0f) lo = mid; else hi = mid;
    }
    const float tau = 0.5f * (lo + hi);

    float* wout = weights + (size_t)b * SS;
    float wv[8];
    int mycnt = 0;
#pragma unroll
    for (int j = 0; j < 8; j++) {
        float d = z[j] - tau;
        d = d > 0.0f ? d : 0.0f;
        const float w = d * d;
        wv[j] = w;
        wout[base + j] = w;
        if (w > 0.0f) mycnt++;
    }
    iscan[tid] = mycnt;
    __syncthreads();
    for (int off = 1; off < 512; off <<= 1) {
        int a = 0;
        if (tid >= off) a = iscan[tid - off];
        __syncthreads();
        iscan[tid] += a;
        __syncthreads();
    }
    int pos = iscan[tid] - mycnt;
#pragma unroll
    for (int j = 0; j < 8; j++) {
        if (wv[j] > 0.0f) {
            g_nzidx[(size_t)b * SS + pos] = base + j;
            g_nzw[(size_t)b * SS + pos]   = wv[j];
            pos++;
        }
    }
    if (tid == 511) g_nzcnt[b] = iscan[511];
}

// ============================================================================
// Kernel 3: sparse context partials + last-block fused reduce.
// grid (B, NPART), 256 threads (one per h).
// ============================================================================
__global__ __launch_bounds__(256) void ctx_sparse_kernel(
    const float* __restrict__ X, float* __restrict__ ctx)
{
    const int b = blockIdx.x;
    const int sl = blockIdx.y;
    const int h = threadIdx.x;

    __shared__ int   sidx[576];
    __shared__ float swt[576];
    __shared__ int   s_last;

    const int cnt = g_nzcnt[b];
    const int per = (cnt + NPART - 1) / NPART;
    const int s0 = sl * per;
    int s1 = s0 + per; if (s1 > cnt) s1 = cnt;
    const int n = s1 - s0;

    for (int t = h; t < n; t += 256) {
        sidx[t] = g_nzidx[(size_t)b * SS + s0 + t];
        swt[t]  = g_nzw[(size_t)b * SS + s0 + t];
    }
    __syncthreads();

    const float* Xb = X + (size_t)b * SS * HH;
    float acc = 0.0f;
    int i = 0;
    for (; i + 8 <= n; i += 8) {
        float x[8];
#pragma unroll
        for (int j = 0; j < 8; j++)
            x[j] = Xb[(size_t)sidx[i + j] * HH + h];
#pragma unroll
        for (int j = 0; j < 8; j++)
            acc = fmaf(x[j], swt[i + j], acc);
    }
    for (; i < n; i++)
        acc = fmaf(Xb[(size_t)sidx[i] * HH + h], swt[i], acc);

    g_partial[((size_t)b * NPART + sl) * HH + h] = acc;

    // last-arriving block for this batch reduces all NPART partials
    __threadfence();
    __syncthreads();
    if (h == 0) {
        const int old = atomicAdd(&g_ctr[b], 1);
        s_last = (old == NPART - 1) ? 1 : 0;
    }
    __syncthreads();
    if (s_last) {
        float s = 0.0f;
#pragma unroll
        for (int c = 0; c < NPART; c++)
            s += ldcg_f32(&g_partial[((size_t)b * NPART + c) * HH + h]);
        ctx[(size_t)b * HH + h] = s;
    }
}

// ============================================================================
extern "C" void kernel_launch(void* const* d_in, const int* in_sizes, int n_in,
                              void* d_out, int out_size)
{
    const float* X  = (const float*)d_in[0];   // [64,4096,256]
    const float* W1 = (const float*)d_in[1];   // [256,128]
    const float* b1 = (const float*)d_in[2];   // [128]
    const float* W2 = (const float*)d_in[3];   // [128,1]
    const float* b2 = (const float*)d_in[4];   // [1]

    float* out = (float*)d_out;
    float* ctx = out;                 // [64,256]  (tuple elem 0)
    float* wts = out + BB * HH;       // [64,4096] (tuple elem 1)

    cudaFuncSetAttribute(scores_mma_kernel,
                         cudaFuncAttributeMaxDynamicSharedMemorySize, SMEM_BYTES);

    convW_kernel<<<128, 256>>>(W1);
    scores_mma_kernel<<<NTOK / 128, 256, SMEM_BYTES>>>(X, b1, W2, b2);
    entmax_kernel<<<BB, 512>>>(wts);
    ctx_sparse_kernel<<<dim3(BB, NPART), 256>>>(X, ctx);
}

// round 13
// speedup vs baseline: 1.6140x; 1.1711x over previous
#include <cuda_runtime.h>
#include <cuda_fp16.h>
#include <cstdint>

// Problem constants
#define BB 64
#define SS 4096
#define HH 256
#define AA 128
#define NTOK (BB * SS)          // 262144 tokens

#define PADK 72                 // fp16 elems per smem row (144B, conflict-free)
#define NPART 8                 // context partial slices per batch

// ---------------- scratch (device globals; no allocation allowed) ----------
__device__ float g_scores[NTOK];                    // [B,S] pre-entmax scores
__device__ float g_partial[BB * NPART * HH];        // context partials
__device__ int   g_nzidx[NTOK];                     // compacted support idx
__device__ float g_nzw[NTOK];                       // compacted support w
__device__ int   g_nzcnt[BB];                       // support count per batch
__device__ int   g_ctr[BB];                         // ctx slice arrival counter
// W1 pre-converted to fp16, padded chunk layout: [4 chunks][128 n][72]
__device__ __half g_Bh[4 * 128 * PADK];

// ---------------- PTX helpers ----------------------------------------------
__device__ __forceinline__ uint32_t s2u(const void* p) {
    uint32_t a;
    asm("{ .reg .u64 t; cvta.to.shared.u64 t, %1; cvt.u32.u64 %0, t; }"
        : "=r"(a) : "l"(p));
    return a;
}

#define LDSM_X4(r0, r1, r2, r3, addr)                                        \
    asm volatile("ldmatrix.sync.aligned.m8n8.x4.shared.b16 {%0,%1,%2,%3}, [%4];" \
                 : "=r"(r0), "=r"(r1), "=r"(r2), "=r"(r3) : "r"(addr))

#define MMA_FP16(d0, d1, d2, d3, a0, a1, a2, a3, b0, b1)                     \
    asm volatile("mma.sync.aligned.m16n8k16.row.col.f32.f16.f16.f32 "       \
                 "{%0,%1,%2,%3}, {%4,%5,%6,%7}, {%8,%9}, {%0,%1,%2,%3};"     \
                 : "+f"(d0), "+f"(d1), "+f"(d2), "+f"(d3)                    \
                 : "r"(a0), "r"(a1), "r"(a2), "r"(a3), "r"(b0), "r"(b1))

#define CP_ASYNC16(dst, src)                                                 \
    asm volatile("cp.async.cg.shared.global [%0], [%1], 16;"                 \
                 :: "r"(dst), "l"(src))
#define CP_COMMIT() asm volatile("cp.async.commit_group;" ::: "memory")
#define CP_WAIT0()  asm volatile("cp.async.wait_group 0;" ::: "memory")

__device__ __forceinline__ float ldcg_f32(const float* p) {
    float v;
    asm volatile("ld.global.cg.f32 %0, [%1];" : "=f"(v) : "l"(p));
    return v;
}

// ============================================================================
// Kernel 0: convert W1 [256,128] fp32 -> fp16, padded chunk layout.
// ============================================================================
__global__ __launch_bounds__(256) void convW_kernel(const float* __restrict__ W1)
{
    const int idx = blockIdx.x * 256 + threadIdx.x;   // 0..32767
    const int k = idx >> 7;       // H index 0..255
    const int n = idx & 127;      // A index 0..127
    const float w = W1[idx];
    const int chunk = k >> 6;
    const int kc = k & 63;
    const int pos = (chunk * 128 + n) * PADK + kc;
    g_Bh[pos] = __float2half_rn(w);
}

// ============================================================================
// Kernel 1: scores GEMM via single-term fp16 mma.sync:
//   D = RN_fp16(X) * RN_fp16(W1), fp32 accumulate.
// One CTA per 128 tokens; 8 warps, warp tile m32 x n64. 16 MMA/warp/kstep.
// ============================================================================
#define OFF_A     0
#define OFF_B     18432
#define OFF_B1S   36864
#define OFF_W2S   37376
#define OFF_SRED  37888
#define SMEM_BYTES 38912

__global__ __launch_bounds__(256, 2) void scores_mma_kernel(
    const float* __restrict__ X,    // [NTOK, 256]
    const float* __restrict__ b1,   // [128]
    const float* __restrict__ W2,   // [128]
    const float* __restrict__ b2)   // [1]
{
    extern __shared__ __align__(16) char smem[];
    const uint32_t sb = s2u(smem);
    const int tid = threadIdx.x;
    const int wid = tid >> 5;
    const int lane = tid & 31;
    const int tok0 = blockIdx.x * 128;

    const int wm = (wid >> 1) * 32;   // warp M origin (0,32,64,96)
    const int wn = (wid & 1) * 64;    // warp N origin (0,64)

    if (tid < 128) {
        *(float*)(smem + OFF_B1S + tid * 4) = b1[tid];
        *(float*)(smem + OFF_W2S + tid * 4) = W2[tid];
    }

    float acc[2][8][4];
#pragma unroll
    for (int mi = 0; mi < 2; mi++)
#pragma unroll
        for (int nf = 0; nf < 8; nf++)
#pragma unroll
            for (int i = 0; i < 4; i++) acc[mi][nf][i] = 0.0f;

    const int row  = tid >> 1;      // 0..127 (token row in tile)
    const int half = tid & 1;       // 32-col half of the 64-col chunk
    const float4* Xr = (const float4*)(X + (size_t)(tok0 + row) * HH);
    const uint32_t a_boff = (uint32_t)row * (PADK * 2) + (uint32_t)(half * 64);

    const int grp = lane >> 3;
    const uint32_t a_rowl = (uint32_t)((lane & 7) + (grp & 1) * 8);
    const uint32_t a_kad = (uint32_t)((grp >> 1) * 8) * 2;
    const uint32_t b_rowbase = (uint32_t)((lane & 7) + (grp >> 1) * 8);
    const uint32_t b_kad = (uint32_t)((grp & 1) * 8) * 2;

    float4 v[8];
#pragma unroll
    for (int q = 0; q < 8; q++) v[q] = Xr[half * 8 + q];

    for (int c = 0; c < 4; c++) {
        // ---- B chunk via cp.async (18432B) ----
        {
            const char* srcb = (const char*)(g_Bh + c * 128 * PADK);
#pragma unroll
            for (int i = 0; i < 5; i++) {
                const int idx = tid + i * 256;
                if (idx < 1152)
                    CP_ASYNC16(sb + OFF_B + idx * 16, srcb + idx * 16);
            }
            CP_COMMIT();
        }
        // ---- convert staged A chunk -> fp16 ----
        {
#pragma unroll
            for (int q = 0; q < 8; q++) {
                const float4 vv = v[q];
                const __half2 h0 = __floats2half2_rn(vv.x, vv.y);
                const __half2 h1 = __floats2half2_rn(vv.z, vv.w);
                uint2 hw;
                hw.x = *(const uint32_t*)&h0;
                hw.y = *(const uint32_t*)&h1;
                *(uint2*)(smem + OFF_A + a_boff + (uint32_t)(q * 8)) = hw;
            }
        }
        if (c < 3) {
#pragma unroll
            for (int q = 0; q < 8; q++) v[q] = Xr[(c + 1) * 16 + half * 8 + q];
        }
        CP_WAIT0();
        __syncthreads();

        // ---- 4 k-steps of 16, 16 MMA each ----
#pragma unroll
        for (int ks = 0; ks < 4; ks++) {
            const uint32_t k0b = (uint32_t)(ks * 16) * 2;
            uint32_t ah[2][4];
#pragma unroll
            for (int mi = 0; mi < 2; mi++) {
                const uint32_t a_off =
                    ((uint32_t)(wm + mi * 16) + a_rowl) * (PADK * 2) + k0b + a_kad;
                LDSM_X4(ah[mi][0], ah[mi][1], ah[mi][2], ah[mi][3],
                        sb + OFF_A + a_off);
            }
#pragma unroll
            for (int ng = 0; ng < 4; ng++) {
                const uint32_t b_off =
                    ((uint32_t)(wn + ng * 16) + b_rowbase) * (PADK * 2) + k0b + b_kad;
                uint32_t bh0, bh1, bh2, bh3;
                LDSM_X4(bh0, bh1, bh2, bh3, sb + OFF_B + b_off);
#pragma unroll
                for (int mi = 0; mi < 2; mi++) {
                    float* d0 = acc[mi][ng * 2];
                    float* d1 = acc[mi][ng * 2 + 1];
                    MMA_FP16(d0[0], d0[1], d0[2], d0[3],
                             ah[mi][0], ah[mi][1], ah[mi][2], ah[mi][3], bh0, bh1);
                    MMA_FP16(d1[0], d1[1], d1[2], d1[3],
                             ah[mi][0], ah[mi][1], ah[mi][2], ah[mi][3], bh2, bh3);
                }
            }
        }
        __syncthreads();
    }

    // ---- epilogue: tanh dot W2 over warp's 64 cols, then cross-warp add ----
    float* sred = (float*)(smem + OFF_SRED);   // [2][128]
#pragma unroll
    for (int mi = 0; mi < 2; mi++) {
        float s0 = 0.0f, s1 = 0.0f;
#pragma unroll
        for (int nf = 0; nf < 8; nf++) {
            const int c0 = wn + nf * 8 + (lane & 3) * 2;
            const float bb0 = *(const float*)(smem + OFF_B1S + c0 * 4);
            const float bb1v = *(const float*)(smem + OFF_B1S + (c0 + 1) * 4);
            const float ww0 = *(const float*)(smem + OFF_W2S + c0 * 4);
            const float ww1 = *(const float*)(smem + OFF_W2S + (c0 + 1) * 4);
            s0 += tanhf(acc[mi][nf][0] + bb0) * ww0 +
                  tanhf(acc[mi][nf][1] + bb1v) * ww1;
            s1 += tanhf(acc[mi][nf][2] + bb0) * ww0 +
                  tanhf(acc[mi][nf][3] + bb1v) * ww1;
        }
        s0 += __shfl_xor_sync(0xffffffffu, s0, 1);
        s0 += __shfl_xor_sync(0xffffffffu, s0, 2);
        s1 += __shfl_xor_sync(0xffffffffu, s1, 1);
        s1 += __shfl_xor_sync(0xffffffffu, s1, 2);
        if ((lane & 3) == 0) {
            const int r = wm + mi * 16 + (lane >> 2);
            sred[(wid & 1) * 128 + r]     = s0;
            sred[(wid & 1) * 128 + r + 8] = s1;
        }
    }
    __syncthreads();
    if (tid < 128)
        g_scores[tok0 + tid] = sred[tid] + sred[128 + tid] + b2[0];
}

// ============================================================================
// Kernel 2: entmax-1.5 per batch row via fixed-count bisection (no sort)
// + deterministic support compaction to global. Also resets g_ctr[b].
// ============================================================================
__global__ __launch_bounds__(512) void entmax_kernel(float* __restrict__ weights)
{
    const int b = blockIdx.x;
    const int tid = threadIdx.x;
    const int wid = tid >> 5;
    const int lane = tid & 31;

    __shared__ float red[16];
    __shared__ float s_bc;
    __shared__ int iscan[512];

    if (tid == 0) g_ctr[b] = 0;     // reset ctx arrival counter each replay

    const float* sc = g_scores + (size_t)b * SS;
    const int base = tid * 8;

    float z[8];
    {
        const float4 p0 = ((const float4*)sc)[tid * 2];
        const float4 p1 = ((const float4*)sc)[tid * 2 + 1];
        z[0] = 0.5f * p0.x; z[1] = 0.5f * p0.y;
        z[2] = 0.5f * p0.z; z[3] = 0.5f * p0.w;
        z[4] = 0.5f * p1.x; z[5] = 0.5f * p1.y;
        z[6] = 0.5f * p1.z; z[7] = 0.5f * p1.w;
    }

    float m = z[0];
#pragma unroll
    for (int j = 1; j < 8; j++) m = fmaxf(m, z[j]);
#pragma unroll
    for (int o = 16; o > 0; o >>= 1) m = fmaxf(m, __shfl_xor_sync(0xffffffffu, m, o));
    if (lane == 0) red[wid] = m;
    __syncthreads();
    if (tid == 0) {
        float t = red[0];
#pragma unroll
        for (int i = 1; i < 16; i++) t = fmaxf(t, red[i]);
        s_bc = t;
    }
    __syncthreads();
    const float mx = s_bc;
#pragma unroll
    for (int j = 0; j < 8; j++) z[j] -= mx;

    float lo = -1.0f, hi = 0.0f;
    for (int it = 0; it < 30; it++) {
        const float mid = 0.5f * (lo + hi);
        float s = 0.0f;
#pragma unroll
        for (int j = 0; j < 8; j++) {
            float d = z[j] - mid;
            d = d > 0.0f ? d : 0.0f;
            s = fmaf(d, d, s);
        }
#pragma unroll
        for (int o = 16; o > 0; o >>= 1) s += __shfl_xor_sync(0xffffffffu, s, o);
        if (lane == 0) red[wid] = s;
        __syncthreads();
        float tot = 0.0f;
#pragma unroll
        for (int i = 0; i < 16; i++) tot += red[i];
        __syncthreads();
        if (tot >= 1.0f) lo = mid; else hi = mid;
    }
    const float tau = 0.5f * (lo + hi);

    float* wout = weights + (size_t)b * SS;
    float wv[8];
    int mycnt = 0;
#pragma unroll
    for (int j = 0; j < 8; j++) {
        float d = z[j] - tau;
        d = d > 0.0f ? d : 0.0f;
        const float w = d * d;
        wv[j] = w;
        wout[base + j] = w;
        if (w > 0.0f) mycnt++;
    }
    iscan[tid] = mycnt;
    __syncthreads();
    for (int off = 1; off < 512; off <<= 1) {
        int a = 0;
        if (tid >= off) a = iscan[tid - off];
        __syncthreads();
        iscan[tid] += a;
        __syncthreads();
    }
    int pos = iscan[tid] - mycnt;
#pragma unroll
    for (int j = 0; j < 8; j++) {
        if (wv[j] > 0.0f) {
            g_nzidx[(size_t)b * SS + pos] = base + j;
            g_nzw[(size_t)b * SS + pos]   = wv[j];
            pos++;
        }
    }
    if (tid == 511) g_nzcnt[b] = iscan[511];
}

// ============================================================================
// Kernel 3: sparse context partials + last-block fused reduce.
// grid (B, NPART), 256 threads (one per h).
// ============================================================================
__global__ __launch_bounds__(256) void ctx_sparse_kernel(
    const float* __restrict__ X, float* __restrict__ ctx)
{
    const int b = blockIdx.x;
    const int sl = blockIdx.y;
    const int h = threadIdx.x;

    __shared__ int   sidx[576];
    __shared__ float swt[576];
    __shared__ int   s_last;

    const int cnt = g_nzcnt[b];
    const int per = (cnt + NPART - 1) / NPART;
    const int s0 = sl * per;
    int s1 = s0 + per; if (s1 > cnt) s1 = cnt;
    const int n = s1 - s0;

    for (int t = h; t < n; t += 256) {
        sidx[t] = g_nzidx[(size_t)b * SS + s0 + t];
        swt[t]  = g_nzw[(size_t)b * SS + s0 + t];
    }
    __syncthreads();

    const float* Xb = X + (size_t)b * SS * HH;
    float acc = 0.0f;
    int i = 0;
    for (; i + 8 <= n; i += 8) {
        float x[8];
#pragma unroll
        for (int j = 0; j < 8; j++)
            x[j] = Xb[(size_t)sidx[i + j] * HH + h];
#pragma unroll
        for (int j = 0; j < 8; j++)
            acc = fmaf(x[j], swt[i + j], acc);
    }
    for (; i < n; i++)
        acc = fmaf(Xb[(size_t)sidx[i] * HH + h], swt[i], acc);

    g_partial[((size_t)b * NPART + sl) * HH + h] = acc;

    // last-arriving block for this batch reduces all NPART partials
    __threadfence();
    __syncthreads();
    if (h == 0) {
        const int old = atomicAdd(&g_ctr[b], 1);
        s_last = (old == NPART - 1) ? 1 : 0;
    }
    __syncthreads();
    if (s_last) {
        float s = 0.0f;
#pragma unroll
        for (int c = 0; c < NPART; c++)
            s += ldcg_f32(&g_partial[((size_t)b * NPART + c) * HH + h]);
        ctx[(size_t)b * HH + h] = s;
    }
}

// ============================================================================
extern "C" void kernel_launch(void* const* d_in, const int* in_sizes, int n_in,
                              void* d_out, int out_size)
{
    const float* X  = (const float*)d_in[0];   // [64,4096,256]
    const float* W1 = (const float*)d_in[1];   // [256,128]
    const float* b1 = (const float*)d_in[2];   // [128]
    const float* W2 = (const float*)d_in[3];   // [128,1]
    const float* b2 = (const float*)d_in[4];   // [1]

    float* out = (float*)d_out;
    float* ctx = out;                 // [64,256]  (tuple elem 0)
    float* wts = out + BB * HH;       // [64,4096] (tuple elem 1)

    cudaFuncSetAttribute(scores_mma_kernel,
                         cudaFuncAttributeMaxDynamicSharedMemorySize, SMEM_BYTES);

    convW_kernel<<<128, 256>>>(W1);
    scores_mma_kernel<<<NTOK / 128, 256, SMEM_BYTES>>>(X, b1, W2, b2);
    entmax_kernel<<<BB, 512>>>(wts);
    ctx_sparse_kernel<<<dim3(BB, NPART), 256>>>(X, ctx);
}